// round 5
// baseline (speedup 1.0000x reference)
#include <cuda_runtime.h>
#include <cuda_bf16.h>
#include <cuda_fp16.h>
#include <math.h>

#define MAXN 100000
#define MAXE 1600000

// ---------------- device scratch ----------------
__device__ uint2  g_h1h[MAXN * 32];   // layer1 features, fp16x4 per uint2 (128/node)
__device__ float4 g_x2v[MAXN * 32];   // layer1 output / layer2 input (fp32)
__device__ uint2  g_h2h[MAXN * 16];   // layer2 pre-agg features, fp16x4 per uint2 (64/node)
__device__ float g_as1[MAXN * 4];
__device__ float g_ad1[MAXN * 4];
__device__ float g_as2[MAXN];
__device__ float g_ad2[MAXN];
__device__ int   g_xi[MAXN];
__device__ int   g_srcb[MAXE];
__device__ int   g_dstb[MAXE];
__device__ int   g_deg[MAXN];
__device__ int   g_off[MAXN + 1];
__device__ int   g_cur[MAXN];
__device__ int   g_csr[MAXE];
__device__ int   g_bsum[512];
__device__ int   g_is64;

// packed fp32x2 FMA (sm_10x; only reachable via PTX)
__device__ __forceinline__ void fma2(unsigned long long& acc,
                                     unsigned long long a,
                                     unsigned long long b) {
    asm("fma.rn.f32x2 %0, %1, %2, %0;" : "+l"(acc) : "l"(a), "l"(b));
}
__device__ __forceinline__ unsigned long long pk2(float lo, float hi) {
    unsigned long long r;
    asm("mov.b64 %0, {%1, %2};" : "=l"(r) : "f"(lo), "f"(hi));
    return r;
}
__device__ __forceinline__ float2 upk2(unsigned long long v) {
    float2 r;
    asm("mov.b64 {%0, %1}, %2;" : "=f"(r.x), "=f"(r.y) : "l"(v));
    return r;
}

// ---------------- dtype sniff + index normalization ----------------
__global__ void k_flag(const int* __restrict__ xw) {
    g_is64 = (xw[1] == 0) ? 1 : 0;
}

__global__ void k_conv_idx(const void* __restrict__ xidx, int n) {
    int i = blockIdx.x * blockDim.x + threadIdx.x;
    if (i >= n) return;
    g_xi[i] = g_is64 ? (int)((const long long*)xidx)[i] : ((const int*)xidx)[i];
    g_deg[i] = 0;
}

__global__ void k_conv_ei(const void* __restrict__ ei, int e) {
    int i = blockIdx.x * blockDim.x + threadIdx.x;
    if (i >= e) return;
    int s, d;
    if (g_is64) {
        s = (int)((const long long*)ei)[i];
        d = (int)((const long long*)ei)[(long long)e + i];
    } else {
        s = ((const int*)ei)[i];
        d = ((const int*)ei)[e + i];
    }
    g_srcb[i] = s;
    g_dstb[i] = d;
    atomicAdd(&g_deg[d], 1);
}

// ---------------- CSR offsets ----------------
__global__ void k_scan1(int n) {
    __shared__ int s[256];
    int tid = threadIdx.x;
    int i = blockIdx.x * 256 + tid;
    int v = (i < n) ? g_deg[i] : 0;
    s[tid] = v;
    __syncthreads();
    for (int o = 1; o < 256; o <<= 1) {
        int t = 0;
        if (tid >= o) t = s[tid - o];
        __syncthreads();
        s[tid] += t;
        __syncthreads();
    }
    int incl = s[tid];
    if (i < n) g_off[i] = incl - v;
    if (tid == 255) g_bsum[blockIdx.x] = incl;
}

__global__ void k_scan2(int nb) {
    __shared__ int s[512];
    int tid = threadIdx.x;
    int v = (tid < nb) ? g_bsum[tid] : 0;
    s[tid] = v;
    __syncthreads();
    for (int o = 1; o < 512; o <<= 1) {
        int t = 0;
        if (tid >= o) t = s[tid - o];
        __syncthreads();
        s[tid] += t;
        __syncthreads();
    }
    if (tid < nb) g_bsum[tid] = s[tid] - v;
}

__global__ void k_scan3(int n, int etot) {
    int i = blockIdx.x * blockDim.x + threadIdx.x;
    if (i < n) {
        int o = g_off[i] + g_bsum[i >> 8];
        g_off[i] = o;
        g_cur[i] = o;
    }
    if (i == 0) g_off[n] = etot;
}

__global__ void k_scatter(int e) {
    int i = blockIdx.x * blockDim.x + threadIdx.x;
    if (i < e) {
        int pos = atomicAdd(&g_cur[g_dstb[i]], 1);
        g_csr[pos] = g_srcb[i];
    }
}

// ---------------- GEMM + fused alpha epilogue ----------------
// LAYER 1: X = emb[g_xi], W [128,128] -> fp16 g_h1h + as1/ad1
// LAYER 2: X = g_x2v,     W [128,64]  -> fp16 g_h2h + as2/ad2
template <int LAYER>
__global__ void __launch_bounds__(128) k_gemm(const float* __restrict__ Xin,
                                              const float* __restrict__ W,
                                              const float* __restrict__ asrc,
                                              const float* __restrict__ adst,
                                              int n) {
    constexpr int COLS = (LAYER == 1) ? 128 : 64;
    constexpr int CT = COLS / 4;      // threads along columns (float4 each)
    constexpr int NG = 128 / CT;      // node groups per block
    constexpr int NPG = 64 / NG;      // nodes per group

    __shared__ float4 Wsh[64 * CT];
    __shared__ float Xsh[64][64];

    const float* X = (LAYER == 1) ? Xin : (const float*)g_x2v;

    const int tid = threadIdx.x;
    const int tx = tid % CT;
    const int ty = tid / CT;
    const int base = blockIdx.x * 64;

    unsigned long long acc2[NPG][2];
#pragma unroll
    for (int i = 0; i < NPG; i++) { acc2[i][0] = 0ull; acc2[i][1] = 0ull; }

    const float4* W4 = (const float4*)W;

    for (int kb = 0; kb < 2; kb++) {
        __syncthreads();
#pragma unroll
        for (int idx = tid; idx < 64 * CT; idx += 128) {
            int row = idx / CT, col = idx % CT;
            Wsh[idx] = W4[(kb * 64 + row) * CT + col];
        }
#pragma unroll 8
        for (int idx = tid; idx < 64 * 64; idx += 128) {
            int r = idx >> 6, k = idx & 63;
            int node = base + r;
            float v = 0.f;
            if (node < n) {
                int g = (LAYER == 1) ? g_xi[node] : node;
                v = X[(long long)g * 128 + kb * 64 + k];
            }
            Xsh[r][k] = v;
        }
        __syncthreads();

#pragma unroll 2
        for (int k4 = 0; k4 < 16; k4++) {
            unsigned long long wlo[4], whi[4];
#pragma unroll
            for (int kk = 0; kk < 4; kk++) {
                float4 w = Wsh[(k4 * 4 + kk) * CT + tx];
                wlo[kk] = pk2(w.x, w.y);
                whi[kk] = pk2(w.z, w.w);
            }
#pragma unroll
            for (int i = 0; i < NPG; i++) {
                float4 xv = *(const float4*)&Xsh[ty * NPG + i][k4 * 4];
                unsigned long long xp;
                xp = pk2(xv.x, xv.x);
                fma2(acc2[i][0], wlo[0], xp);
                fma2(acc2[i][1], whi[0], xp);
                xp = pk2(xv.y, xv.y);
                fma2(acc2[i][0], wlo[1], xp);
                fma2(acc2[i][1], whi[1], xp);
                xp = pk2(xv.z, xv.z);
                fma2(acc2[i][0], wlo[2], xp);
                fma2(acc2[i][1], whi[2], xp);
                xp = pk2(xv.w, xv.w);
                fma2(acc2[i][0], wlo[3], xp);
                fma2(acc2[i][1], whi[3], xp);
            }
        }
    }

    // epilogue: fp16 feature store + fused attention-logit reduction
    const float4 as4 = ((const float4*)asrc)[tx];
    const float4 ad4 = ((const float4*)adst)[tx];
#pragma unroll
    for (int i = 0; i < NPG; i++) {
        int node = base + ty * NPG + i;
        if (node >= n) continue;
        float2 lo = upk2(acc2[i][0]);
        float2 hi = upk2(acc2[i][1]);

        float s = lo.x * as4.x + lo.y * as4.y + hi.x * as4.z + hi.y * as4.w;
        float d = lo.x * ad4.x + lo.y * ad4.y + hi.x * ad4.z + hi.y * ad4.w;

        uint2 p;
        __half2 h0 = __float22half2_rn(make_float2(lo.x, lo.y));
        __half2 h1 = __float22half2_rn(make_float2(hi.x, hi.y));
        p.x = *(unsigned int*)&h0;
        p.y = *(unsigned int*)&h1;

        if (LAYER == 1) {
            g_h1h[node * 32 + tx] = p;
#pragma unroll
            for (int o = 1; o < 8; o <<= 1) {
                s += __shfl_xor_sync(0xffffffffu, s, o);
                d += __shfl_xor_sync(0xffffffffu, d, o);
            }
            if ((tx & 7) == 0) {
                g_as1[node * 4 + (tx >> 3)] = s;
                g_ad1[node * 4 + (tx >> 3)] = d;
            }
        } else {
            g_h2h[node * 16 + tx] = p;
#pragma unroll
            for (int o = 1; o < 16; o <<= 1) {
                s += __shfl_xor_sync(0xffffffffu, s, o);
                d += __shfl_xor_sync(0xffffffffu, d, o);
            }
            if (tx == 0) {
                g_as2[node] = s;
                g_ad2[node] = d;
            }
        }
    }
}

__device__ __forceinline__ float att_w(float e) {
    float lr = (e > 0.f) ? e : 0.2f * e;
    return __expf(lr);
}

// ---------------- fused gather layer 1 (fp16): softmax-agg + bias + ELU ----------------
__global__ void k_gather1(const float* __restrict__ b1, int n) {
    int node = (blockIdx.x * blockDim.x + threadIdx.x) >> 5;
    int lane = threadIdx.x & 31;
    if (node >= n) return;
    int head = lane >> 3;

    float ad = g_ad1[node * 4 + head];

    // self loop
    float w = att_w(g_as1[node * 4 + head] + ad);
    uint2 p = g_h1h[node * 32 + lane];
    float2 f0 = __half22float2(*(const __half2*)&p.x);
    float2 f1 = __half22float2(*(const __half2*)&p.y);
    float4 acc = make_float4(w * f0.x, w * f0.y, w * f1.x, w * f1.y);
    float wsum = w;

    int i = g_off[node];
    int iend = g_off[node + 1];
    // unroll-by-2: two edges in flight (doubles memory-level parallelism)
    for (; i + 2 <= iend; i += 2) {
        int s0 = g_csr[i];
        int s1 = g_csr[i + 1];
        float a0 = g_as1[s0 * 4 + head];
        float a1 = g_as1[s1 * 4 + head];
        uint2 q0 = g_h1h[s0 * 32 + lane];
        uint2 q1 = g_h1h[s1 * 32 + lane];
        float w0 = att_w(a0 + ad);
        float w1 = att_w(a1 + ad);
        float2 u0 = __half22float2(*(const __half2*)&q0.x);
        float2 u1 = __half22float2(*(const __half2*)&q0.y);
        float2 v0 = __half22float2(*(const __half2*)&q1.x);
        float2 v1 = __half22float2(*(const __half2*)&q1.y);
        acc.x += w0 * u0.x + w1 * v0.x;
        acc.y += w0 * u0.y + w1 * v0.y;
        acc.z += w0 * u1.x + w1 * v1.x;
        acc.w += w0 * u1.y + w1 * v1.y;
        wsum += w0 + w1;
    }
    if (i < iend) {
        int src = g_csr[i];
        float ww = att_w(g_as1[src * 4 + head] + ad);
        uint2 q = g_h1h[src * 32 + lane];
        float2 v0 = __half22float2(*(const __half2*)&q.x);
        float2 v1 = __half22float2(*(const __half2*)&q.y);
        acc.x += ww * v0.x;
        acc.y += ww * v0.y;
        acc.z += ww * v1.x;
        acc.w += ww * v1.y;
        wsum += ww;
    }
    float inv = 1.f / wsum;
    float4 bb = ((const float4*)b1)[lane];
    float ox = acc.x * inv + bb.x;
    float oy = acc.y * inv + bb.y;
    float oz = acc.z * inv + bb.z;
    float ow = acc.w * inv + bb.w;
    ox = (ox > 0.f) ? ox : expm1f(ox);
    oy = (oy > 0.f) ? oy : expm1f(oy);
    oz = (oz > 0.f) ? oz : expm1f(oz);
    ow = (ow > 0.f) ? ow : expm1f(ow);
    g_x2v[node * 32 + lane] = make_float4(ox, oy, oz, ow);
}

// ---------------- fused gather layer 2 (fp16): softmax-agg + bias ----------------
__global__ void k_gather2(const float* __restrict__ b2, float* __restrict__ out, int n) {
    int node = (blockIdx.x * blockDim.x + threadIdx.x) >> 5;
    int lane = threadIdx.x & 31;
    if (node >= n) return;

    const __half2* H2 = (const __half2*)g_h2h;   // 32 half2 per node
    float ad = g_ad2[node];

    float w = att_w(g_as2[node] + ad);
    float2 hv = __half22float2(H2[node * 32 + lane]);
    float2 acc = make_float2(w * hv.x, w * hv.y);
    float wsum = w;

    int i = g_off[node];
    int iend = g_off[node + 1];
    for (; i + 2 <= iend; i += 2) {
        int s0 = g_csr[i];
        int s1 = g_csr[i + 1];
        float a0 = g_as2[s0];
        float a1 = g_as2[s1];
        __half2 q0 = H2[s0 * 32 + lane];
        __half2 q1 = H2[s1 * 32 + lane];
        float w0 = att_w(a0 + ad);
        float w1 = att_w(a1 + ad);
        float2 u = __half22float2(q0);
        float2 v = __half22float2(q1);
        acc.x += w0 * u.x + w1 * v.x;
        acc.y += w0 * u.y + w1 * v.y;
        wsum += w0 + w1;
    }
    if (i < iend) {
        int src = g_csr[i];
        float ww = att_w(g_as2[src] + ad);
        float2 v = __half22float2(H2[src * 32 + lane]);
        acc.x += ww * v.x;
        acc.y += ww * v.y;
        wsum += ww;
    }
    float inv = 1.f / wsum;
    float2 bb = ((const float2*)b2)[lane];
    ((float2*)out)[node * 32 + lane] =
        make_float2(acc.x * inv + bb.x, acc.y * inv + bb.y);
}

// ---------------- launch ----------------
extern "C" void kernel_launch(void* const* d_in, const int* in_sizes, int n_in,
                              void* d_out, int out_size) {
    const void* xidx = d_in[0];
    const void* ei = d_in[1];
    const float* emb = (const float*)d_in[2];
    const float* W1 = (const float*)d_in[3];
    const float* a_src1 = (const float*)d_in[4];
    const float* a_dst1 = (const float*)d_in[5];
    const float* b1 = (const float*)d_in[6];
    const float* W2 = (const float*)d_in[7];
    const float* a_src2 = (const float*)d_in[8];
    const float* a_dst2 = (const float*)d_in[9];
    const float* b2 = (const float*)d_in[10];
    float* out = (float*)d_out;

    int n = in_sizes[0];
    int e = in_sizes[1] / 2;

    int nb256 = (n + 255) / 256;
    int eb256 = (e + 255) / 256;
    int nwarp = (n + 7) / 8;
    int gb = (n + 63) / 64;

    k_flag<<<1, 1>>>((const int*)xidx);
    k_conv_idx<<<nb256, 256>>>(xidx, n);
    k_conv_ei<<<eb256, 256>>>(ei, e);

    k_scan1<<<nb256, 256>>>(n);
    k_scan2<<<1, 512>>>(nb256);
    k_scan3<<<nb256, 256>>>(n, e);
    k_scatter<<<eb256, 256>>>(e);

    k_gemm<1><<<gb, 128>>>(emb, W1, a_src1, a_dst1, n);
    k_gather1<<<nwarp, 256>>>(b1, n);

    k_gemm<2><<<gb, 128>>>(nullptr, W2, a_src2, a_dst2, n);
    k_gather2<<<nwarp, 256>>>(b2, out, n);
}

// round 6
// speedup vs baseline: 1.0753x; 1.0753x over previous
#include <cuda_runtime.h>
#include <cuda_bf16.h>
#include <cuda_fp16.h>
#include <math.h>

#define MAXN 100000
#define MAXE 1600000

// ---------------- device scratch ----------------
__device__ uint2  g_h1h[MAXN * 32];   // layer1 features, fp16x4 per uint2 (128/node)
__device__ float4 g_x2v[MAXN * 32];   // layer1 output / layer2 input (fp32)
__device__ uint2  g_h2h[MAXN * 16];   // layer2 pre-agg features, fp16x4 (64/node)
__device__ float g_as1[MAXN * 4];
__device__ float g_ad1[MAXN * 4];
__device__ float g_as2[MAXN];
__device__ float g_ad2[MAXN];
__device__ int   g_xi[MAXN];
__device__ int   g_srcb[MAXE];
__device__ int   g_dstb[MAXE];
__device__ int   g_deg[MAXN];
__device__ int   g_off[MAXN + 1];
__device__ int   g_cur[MAXN];
__device__ int   g_csr[MAXE];
__device__ int   g_bsum[512];

// packed fp32x2 FMA (sm_10x; only reachable via PTX)
__device__ __forceinline__ void fma2(unsigned long long& acc,
                                     unsigned long long a,
                                     unsigned long long b) {
    asm("fma.rn.f32x2 %0, %1, %2, %0;" : "+l"(acc) : "l"(a), "l"(b));
}
__device__ __forceinline__ unsigned long long pk2(float lo, float hi) {
    unsigned long long r;
    asm("mov.b64 %0, {%1, %2};" : "=l"(r) : "f"(lo), "f"(hi));
    return r;
}
__device__ __forceinline__ float2 upk2(unsigned long long v) {
    float2 r;
    asm("mov.b64 {%0, %1}, %2;" : "=f"(r.x), "=f"(r.y) : "l"(v));
    return r;
}

// dtype sniff: x_indices = arange(N). int64 little-endian => word[1] (high half
// of element 0) == 0; int32 => word[1] == element 1 == 1.
__device__ __forceinline__ bool sniff64(const int* xw) { return xw[1] == 0; }

// ---------------- index normalization (dtype-robust) ----------------
__global__ void k_conv_idx(const void* __restrict__ xidx, int n) {
    int i = blockIdx.x * blockDim.x + threadIdx.x;
    if (i >= n) return;
    bool is64 = sniff64((const int*)xidx);
    g_xi[i] = is64 ? (int)((const long long*)xidx)[i] : ((const int*)xidx)[i];
    g_deg[i] = 0;
}

__global__ void k_conv_ei(const void* __restrict__ ei,
                          const void* __restrict__ xidx, int e) {
    int i = blockIdx.x * blockDim.x + threadIdx.x;
    if (i >= e) return;
    bool is64 = sniff64((const int*)xidx);
    int s, d;
    if (is64) {
        s = (int)((const long long*)ei)[i];
        d = (int)((const long long*)ei)[(long long)e + i];
    } else {
        s = ((const int*)ei)[i];
        d = ((const int*)ei)[e + i];
    }
    g_srcb[i] = s;
    g_dstb[i] = d;
    atomicAdd(&g_deg[d], 1);
}

// ---------------- CSR offsets ----------------
__global__ void k_scan1(int n) {
    __shared__ int s[256];
    int tid = threadIdx.x;
    int i = blockIdx.x * 256 + tid;
    int v = (i < n) ? g_deg[i] : 0;
    s[tid] = v;
    __syncthreads();
    for (int o = 1; o < 256; o <<= 1) {
        int t = 0;
        if (tid >= o) t = s[tid - o];
        __syncthreads();
        s[tid] += t;
        __syncthreads();
    }
    int incl = s[tid];
    if (i < n) g_off[i] = incl - v;
    if (tid == 255) g_bsum[blockIdx.x] = incl;
}

__global__ void k_scan2(int nb) {
    __shared__ int s[512];
    int tid = threadIdx.x;
    int v = (tid < nb) ? g_bsum[tid] : 0;
    s[tid] = v;
    __syncthreads();
    for (int o = 1; o < 512; o <<= 1) {
        int t = 0;
        if (tid >= o) t = s[tid - o];
        __syncthreads();
        s[tid] += t;
        __syncthreads();
    }
    if (tid < nb) g_bsum[tid] = s[tid] - v;
}

__global__ void k_scan3(int n, int etot) {
    int i = blockIdx.x * blockDim.x + threadIdx.x;
    if (i < n) {
        int o = g_off[i] + g_bsum[i >> 8];
        g_off[i] = o;
        g_cur[i] = o;
    }
    if (i == 0) g_off[n] = etot;
}

// ---------------- GEMM + fused alpha epilogue (+ fused CSR scatter, layer 1) ----------------
// LAYER 1: X = emb[g_xi], W [128,128] -> fp16 g_h1h + as1/ad1 ; extra blocks do scatter
// LAYER 2: X = g_x2v,     W [128,64]  -> fp16 g_h2h + as2/ad2
template <int LAYER>
__global__ void __launch_bounds__(128) k_gemm(const float* __restrict__ Xin,
                                              const float* __restrict__ W,
                                              const float* __restrict__ asrc,
                                              const float* __restrict__ adst,
                                              int n, int gb, int e) {
    // trailing blocks: CSR scatter (memory-only, overlaps with GEMM compute)
    if (LAYER == 1 && (int)blockIdx.x >= gb) {
        int i = (blockIdx.x - gb) * 128 + threadIdx.x;
        if (i < e) {
            int pos = atomicAdd(&g_cur[g_dstb[i]], 1);
            g_csr[pos] = g_srcb[i];
        }
        return;
    }

    constexpr int COLS = (LAYER == 1) ? 128 : 64;
    constexpr int CT = COLS / 4;      // threads along columns (float4 each)
    constexpr int NG = 128 / CT;      // node groups per block
    constexpr int NPG = 64 / NG;      // nodes per group

    __shared__ float4 Wsh[64 * CT];
    __shared__ float Xsh[64][64];

    const float* X = (LAYER == 1) ? Xin : (const float*)g_x2v;

    const int tid = threadIdx.x;
    const int tx = tid % CT;
    const int ty = tid / CT;
    const int base = blockIdx.x * 64;

    unsigned long long acc2[NPG][2];
#pragma unroll
    for (int i = 0; i < NPG; i++) { acc2[i][0] = 0ull; acc2[i][1] = 0ull; }

    const float4* W4 = (const float4*)W;

    for (int kb = 0; kb < 2; kb++) {
        __syncthreads();
#pragma unroll
        for (int idx = tid; idx < 64 * CT; idx += 128) {
            int row = idx / CT, col = idx % CT;
            Wsh[idx] = W4[(kb * 64 + row) * CT + col];
        }
#pragma unroll 8
        for (int idx = tid; idx < 64 * 64; idx += 128) {
            int r = idx >> 6, k = idx & 63;
            int node = base + r;
            float v = 0.f;
            if (node < n) {
                int g = (LAYER == 1) ? g_xi[node] : node;
                v = X[(long long)g * 128 + kb * 64 + k];
            }
            Xsh[r][k] = v;
        }
        __syncthreads();

#pragma unroll 2
        for (int k4 = 0; k4 < 16; k4++) {
            unsigned long long wlo[4], whi[4];
#pragma unroll
            for (int kk = 0; kk < 4; kk++) {
                float4 w = Wsh[(k4 * 4 + kk) * CT + tx];
                wlo[kk] = pk2(w.x, w.y);
                whi[kk] = pk2(w.z, w.w);
            }
#pragma unroll
            for (int i = 0; i < NPG; i++) {
                float4 xv = *(const float4*)&Xsh[ty * NPG + i][k4 * 4];
                unsigned long long xp;
                xp = pk2(xv.x, xv.x);
                fma2(acc2[i][0], wlo[0], xp);
                fma2(acc2[i][1], whi[0], xp);
                xp = pk2(xv.y, xv.y);
                fma2(acc2[i][0], wlo[1], xp);
                fma2(acc2[i][1], whi[1], xp);
                xp = pk2(xv.z, xv.z);
                fma2(acc2[i][0], wlo[2], xp);
                fma2(acc2[i][1], whi[2], xp);
                xp = pk2(xv.w, xv.w);
                fma2(acc2[i][0], wlo[3], xp);
                fma2(acc2[i][1], whi[3], xp);
            }
        }
    }

    // epilogue: fp16 feature store + fused attention-logit reduction
    const float4 as4 = ((const float4*)asrc)[tx];
    const float4 ad4 = ((const float4*)adst)[tx];
#pragma unroll
    for (int i = 0; i < NPG; i++) {
        int node = base + ty * NPG + i;
        if (node >= n) continue;
        float2 lo = upk2(acc2[i][0]);
        float2 hi = upk2(acc2[i][1]);

        float s = lo.x * as4.x + lo.y * as4.y + hi.x * as4.z + hi.y * as4.w;
        float d = lo.x * ad4.x + lo.y * ad4.y + hi.x * ad4.z + hi.y * ad4.w;

        uint2 p;
        __half2 h0 = __float22half2_rn(make_float2(lo.x, lo.y));
        __half2 h1 = __float22half2_rn(make_float2(hi.x, hi.y));
        p.x = *(unsigned int*)&h0;
        p.y = *(unsigned int*)&h1;

        if (LAYER == 1) {
            g_h1h[node * 32 + tx] = p;
#pragma unroll
            for (int o = 1; o < 8; o <<= 1) {
                s += __shfl_xor_sync(0xffffffffu, s, o);
                d += __shfl_xor_sync(0xffffffffu, d, o);
            }
            if ((tx & 7) == 0) {
                g_as1[node * 4 + (tx >> 3)] = s;
                g_ad1[node * 4 + (tx >> 3)] = d;
            }
        } else {
            g_h2h[node * 16 + tx] = p;
#pragma unroll
            for (int o = 1; o < 16; o <<= 1) {
                s += __shfl_xor_sync(0xffffffffu, s, o);
                d += __shfl_xor_sync(0xffffffffu, d, o);
            }
            if (tx == 0) {
                g_as2[node] = s;
                g_ad2[node] = d;
            }
        }
    }
}

__device__ __forceinline__ float att_w(float e) {
    float lr = (e > 0.f) ? e : 0.2f * e;
    return __expf(lr);
}

// ---------------- fused gather layer 1 (fp16): softmax-agg + bias + ELU ----------------
__global__ void k_gather1(const float* __restrict__ b1, int n) {
    int node = (blockIdx.x * blockDim.x + threadIdx.x) >> 5;
    int lane = threadIdx.x & 31;
    if (node >= n) return;
    int head = lane >> 3;

    float ad = g_ad1[node * 4 + head];

    // self loop
    float w = att_w(g_as1[node * 4 + head] + ad);
    uint2 p = g_h1h[node * 32 + lane];
    float2 f0 = __half22float2(*(const __half2*)&p.x);
    float2 f1 = __half22float2(*(const __half2*)&p.y);
    float4 acc = make_float4(w * f0.x, w * f0.y, w * f1.x, w * f1.y);
    float wsum = w;

    int i = g_off[node];
    int iend = g_off[node + 1];
    for (; i < iend; i++) {
        int src = g_csr[i];
        float ww = att_w(g_as1[src * 4 + head] + ad);
        uint2 q = g_h1h[src * 32 + lane];
        float2 v0 = __half22float2(*(const __half2*)&q.x);
        float2 v1 = __half22float2(*(const __half2*)&q.y);
        acc.x += ww * v0.x;
        acc.y += ww * v0.y;
        acc.z += ww * v1.x;
        acc.w += ww * v1.y;
        wsum += ww;
    }
    float inv = 1.f / wsum;
    float4 bb = ((const float4*)b1)[lane];
    float ox = acc.x * inv + bb.x;
    float oy = acc.y * inv + bb.y;
    float oz = acc.z * inv + bb.z;
    float ow = acc.w * inv + bb.w;
    ox = (ox > 0.f) ? ox : expm1f(ox);
    oy = (oy > 0.f) ? oy : expm1f(oy);
    oz = (oz > 0.f) ? oz : expm1f(oz);
    ow = (ow > 0.f) ? ow : expm1f(ow);
    g_x2v[node * 32 + lane] = make_float4(ox, oy, oz, ow);
}

// ---------------- fused gather layer 2 (fp16): softmax-agg + bias ----------------
__global__ void k_gather2(const float* __restrict__ b2, float* __restrict__ out, int n) {
    int node = (blockIdx.x * blockDim.x + threadIdx.x) >> 5;
    int lane = threadIdx.x & 31;
    if (node >= n) return;

    const __half2* H2 = (const __half2*)g_h2h;   // 32 half2 per node
    float ad = g_ad2[node];

    float w = att_w(g_as2[node] + ad);
    float2 hv = __half22float2(H2[node * 32 + lane]);
    float2 acc = make_float2(w * hv.x, w * hv.y);
    float wsum = w;

    int i = g_off[node];
    int iend = g_off[node + 1];
    for (; i < iend; i++) {
        int src = g_csr[i];
        float ww = att_w(g_as2[src] + ad);
        float2 v = __half22float2(H2[src * 32 + lane]);
        acc.x += ww * v.x;
        acc.y += ww * v.y;
        wsum += ww;
    }
    float inv = 1.f / wsum;
    float2 bb = ((const float2*)b2)[lane];
    ((float2*)out)[node * 32 + lane] =
        make_float2(acc.x * inv + bb.x, acc.y * inv + bb.y);
}

// ---------------- launch ----------------
extern "C" void kernel_launch(void* const* d_in, const int* in_sizes, int n_in,
                              void* d_out, int out_size) {
    const void* xidx = d_in[0];
    const void* ei = d_in[1];
    const float* emb = (const float*)d_in[2];
    const float* W1 = (const float*)d_in[3];
    const float* a_src1 = (const float*)d_in[4];
    const float* a_dst1 = (const float*)d_in[5];
    const float* b1 = (const float*)d_in[6];
    const float* W2 = (const float*)d_in[7];
    const float* a_src2 = (const float*)d_in[8];
    const float* a_dst2 = (const float*)d_in[9];
    const float* b2 = (const float*)d_in[10];
    float* out = (float*)d_out;

    int n = in_sizes[0];
    int e = in_sizes[1] / 2;

    int nb256 = (n + 255) / 256;
    int eb256 = (e + 255) / 256;
    int nwarp = (n + 7) / 8;
    int gb = (n + 63) / 64;
    int eb128 = (e + 127) / 128;

    k_conv_idx<<<nb256, 256>>>(xidx, n);
    k_conv_ei<<<eb256, 256>>>(ei, xidx, e);

    k_scan1<<<nb256, 256>>>(n);
    k_scan2<<<1, 512>>>(nb256);
    k_scan3<<<nb256, 256>>>(n, e);

    // fused: GEMM1 (+alpha epilogue) and CSR scatter in one launch
    k_gemm<1><<<gb + eb128, 128>>>(emb, W1, a_src1, a_dst1, n, gb, e);
    k_gather1<<<nwarp, 256>>>(b1, n);

    k_gemm<2><<<gb, 128>>>(nullptr, W2, a_src2, a_dst2, n, gb, 0);
    k_gather2<<<nwarp, 256>>>(b2, out, n);
}